// round 13
// baseline (speedup 1.0000x reference)
#include <cuda_runtime.h>
#include <cuda_bf16.h>
#include <math.h>
#include <stdint.h>

#define BATCH 8
#define CH 128
#define NTOK 4096          // H*W
#define NGRP 32
#define CPG 4
#define EPSV 1e-5f
#define ATT_SCALE 0.08838834764831845f        // 1/sqrt(128)
#define QSC (ATT_SCALE * 1.4426950408889634f) // fold log2(e): exp -> ex2

// scratch (static device globals; no allocation allowed)
__device__ float g_normed[BATCH*CH*NTOK];            // NCHW
__device__ float g_q[BATCH*NTOK*CH];                 // token-major, CH-permuted
__device__ __nv_bfloat16 g_kb[BATCH*NTOK*CH];        // token-major, CH-permuted
__device__ __nv_bfloat16 g_vb[BATCH*CH*NTOK];        // channel-major, key-permuted
__device__ float g_attn[BATCH*NTOK*CH];
__device__ float g_mean[BATCH*NGRP];
__device__ float g_rstd[BATCH*NGRP];

// ---------------------------------------------------------------------------
// helpers
// ---------------------------------------------------------------------------
__device__ __forceinline__ unsigned f2tf(float f) {
    unsigned r;
    asm("cvt.rna.tf32.f32 %0, %1;" : "=r"(r) : "f"(f));
    return r;
}
__device__ __forceinline__ float ex2(float x) {
    float r;
    asm("ex2.approx.ftz.f32 %0, %1;" : "=f"(r) : "f"(x));
    return r;
}
// pack (lo, hi) floats into bf16x2 register (lo in low half)
__device__ __forceinline__ unsigned bfpack(float lo, float hi) {
    unsigned d;
    asm("cvt.rn.bf16x2.f32 %0, %1, %2;" : "=r"(d) : "f"(hi), "f"(lo));
    return d;
}
// tf32 m16n8k8 (qkv/proj)
__device__ __forceinline__ void mma8(float* d, const unsigned* a, unsigned b0, unsigned b1) {
    asm volatile(
        "mma.sync.aligned.m16n8k8.row.col.f32.tf32.tf32.f32 "
        "{%0,%1,%2,%3}, {%4,%5,%6,%7}, {%8,%9}, {%0,%1,%2,%3};"
        : "+f"(d[0]), "+f"(d[1]), "+f"(d[2]), "+f"(d[3])
        : "r"(a[0]), "r"(a[1]), "r"(a[2]), "r"(a[3]), "r"(b0), "r"(b1));
}
// bf16 m16n8k16 (flash)
__device__ __forceinline__ void mma16(float* d, const unsigned* a, unsigned b0, unsigned b1) {
    asm volatile(
        "mma.sync.aligned.m16n8k16.row.col.f32.bf16.bf16.f32 "
        "{%0,%1,%2,%3}, {%4,%5,%6,%7}, {%8,%9}, {%0,%1,%2,%3};"
        : "+f"(d[0]), "+f"(d[1]), "+f"(d[2]), "+f"(d[3])
        : "r"(a[0]), "r"(a[1]), "r"(a[2]), "r"(a[3]), "r"(b0), "r"(b1));
}

// ---------------------------------------------------------------------------
// K1: GroupNorm statistics
// ---------------------------------------------------------------------------
__global__ void gn_stats(const float* __restrict__ x) {
    const int bg = blockIdx.x;
    const float4* p = (const float4*)(x + (size_t)bg * CPG * NTOK);
    const int n4 = CPG * NTOK / 4;
    float s = 0.f, s2 = 0.f;
    for (int i = threadIdx.x; i < n4; i += blockDim.x) {
        float4 v = p[i];
        s  += v.x + v.y + v.z + v.w;
        s2 += v.x*v.x + v.y*v.y + v.z*v.z + v.w*v.w;
    }
    __shared__ float ss[256], ss2[256];
    ss[threadIdx.x] = s; ss2[threadIdx.x] = s2;
    __syncthreads();
    for (int st = 128; st > 0; st >>= 1) {
        if (threadIdx.x < st) {
            ss[threadIdx.x]  += ss[threadIdx.x + st];
            ss2[threadIdx.x] += ss2[threadIdx.x + st];
        }
        __syncthreads();
    }
    if (threadIdx.x == 0) {
        const float invn = 1.0f / (CPG * NTOK);
        float mu  = ss[0] * invn;
        float var = ss2[0] * invn - mu * mu;
        g_mean[bg] = mu;
        g_rstd[bg] = rsqrtf(var + EPSV);
    }
}

// ---------------------------------------------------------------------------
// K2: apply GroupNorm
// ---------------------------------------------------------------------------
__global__ void gn_apply(const float* __restrict__ x,
                         const float* __restrict__ gw,
                         const float* __restrict__ gb) {
    const int idx = blockIdx.x * blockDim.x + threadIdx.x;
    const int c_lin = idx >> 10;
    const int c = c_lin & (CH - 1);
    const int bg = c_lin >> 2;
    const float mu = g_mean[bg], rs = g_rstd[bg];
    const float a = rs * gw[c];
    const float bb = gb[c] - mu * a;
    float4 v = ((const float4*)x)[idx];
    v.x = v.x * a + bb;  v.y = v.y * a + bb;
    v.z = v.z * a + bb;  v.w = v.w * a + bb;
    ((float4*)g_normed)[idx] = v;
}

// ---------------------------------------------------------------------------
// K3: QKV projections via tf32 mma (unchanged — passing)
// ---------------------------------------------------------------------------
__global__ void __launch_bounds__(256) qkv_mma(
        const float* __restrict__ Wq, const float* __restrict__ bq,
        const float* __restrict__ Wk, const float* __restrict__ bk,
        const float* __restrict__ Wv, const float* __restrict__ bv) {
    extern __shared__ unsigned Ws[];
    const int tid = threadIdx.x;
    const int w = tid >> 5, l = tid & 31, g = l >> 2, t = l & 3;
    const int sel = blockIdx.y;
    const float* W    = (sel == 0) ? Wq : (sel == 1 ? Wk : Wv);
    const float* bias = (sel == 0) ? bq : (sel == 1 ? bk : bv);

    #pragma unroll
    for (int o = 0; o < 2; o++) {
        const int n = o * 64 + w * 8 + g;
        #pragma unroll
        for (int i = 0; i < 16; i++) {
            unsigned v0 = f2tf(W[n * CH + i * 8 + t]);
            unsigned v1 = f2tf(W[n * CH + i * 8 + t + 4]);
            const int qs = (4 * i + t) ^ ((n & 3) << 2);
            *(uint2*)&Ws[n * CH + 2 * qs] = make_uint2(v0, v1);
        }
    }
    __syncthreads();

    const int m0 = blockIdx.x * 128;
    const int bb = m0 >> 12;
    const int tok = (m0 & (NTOK - 1)) + w * 16 + g;
    const float* A = g_normed + (size_t)bb * CH * NTOK;

    unsigned aa[16][4];
    #pragma unroll
    for (int kt = 0; kt < 16; kt++) {
        aa[kt][0] = f2tf(A[(size_t)(kt*8 + t    ) * NTOK + tok    ]);
        aa[kt][1] = f2tf(A[(size_t)(kt*8 + t    ) * NTOK + tok + 8]);
        aa[kt][2] = f2tf(A[(size_t)(kt*8 + t + 4) * NTOK + tok    ]);
        aa[kt][3] = f2tf(A[(size_t)(kt*8 + t + 4) * NTOK + tok + 8]);
    }

    float acc[16][4];
    #pragma unroll
    for (int nt = 0; nt < 16; nt++)
        #pragma unroll
        for (int c = 0; c < 4; c++) acc[nt][c] = 0.f;

    const int sw = (g & 3) << 2;
    #pragma unroll
    for (int kt = 0; kt < 16; kt++) {
        const int qs = (kt * 4 + t) ^ sw;
        #pragma unroll
        for (int nt = 0; nt < 16; nt++) {
            uint2 b = *(uint2*)&Ws[(nt*8 + g) * CH + 2 * qs];
            mma8(acc[nt], aa[kt], b.x, b.y);
        }
    }

    const int gm = m0 + w * 16 + g;
    if (sel == 0) {
        // Q fp32, channel-permuted: logical ch nt*8+2t(+1) -> phys 16a+4t+2h(+1)
        #pragma unroll
        for (int nt = 0; nt < 16; nt++) {
            const int chl = nt * 8 + 2 * t;
            const float b0 = bias[chl], b1 = bias[chl + 1];
            const int phys = (nt >> 1) * 16 + 4 * t + (nt & 1) * 2;
            float2 v0 = {acc[nt][0] + b0, acc[nt][1] + b1};
            float2 v1 = {acc[nt][2] + b0, acc[nt][3] + b1};
            *(float2*)&g_q[(size_t)gm * CH + phys]       = v0;
            *(float2*)&g_q[(size_t)(gm + 8) * CH + phys] = v1;
        }
    } else if (sel == 1) {
        // K bf16, channel-permuted
        #pragma unroll
        for (int nt = 0; nt < 16; nt++) {
            const int chl = nt * 8 + 2 * t;
            const float b0 = bias[chl], b1 = bias[chl + 1];
            const int phys = (nt >> 1) * 16 + 4 * t + (nt & 1) * 2;
            __nv_bfloat162 v0, v1;
            v0.x = __float2bfloat16(acc[nt][0] + b0);
            v0.y = __float2bfloat16(acc[nt][1] + b1);
            v1.x = __float2bfloat16(acc[nt][2] + b0);
            v1.y = __float2bfloat16(acc[nt][3] + b1);
            *(__nv_bfloat162*)&g_kb[(size_t)gm * CH + phys]       = v0;
            *(__nv_bfloat162*)&g_kb[(size_t)(gm + 8) * CH + phys] = v1;
        }
    } else {
        // V bf16 channel-major, token-permuted within 16
        const int tloc = gm & (NTOK - 1);
        const int base16 = tloc - g;
        const int pg0 = 4 * (g >> 1) + (g & 1);
        #pragma unroll
        for (int nt = 0; nt < 16; nt++) {
            #pragma unroll
            for (int c = 0; c < 2; c++) {
                const int ch = nt * 8 + 2 * t + c;
                const float bo = bias[ch];
                const size_t a0 = ((size_t)bb * CH + ch) * NTOK + base16 + pg0;
                g_vb[a0]     = __float2bfloat16(acc[nt][c]     + bo);
                g_vb[a0 + 2] = __float2bfloat16(acc[nt][c + 2] + bo);
            }
        }
    }
}

// ---------------------------------------------------------------------------
// K4: bf16 m16n8k16 flash attention, v3 (B-fragment reuse x2).
//  128 threads / 4 warps; each warp owns 32 query rows (two 16-row A-sets),
//  so every K/V B-fragment lds.64 feeds TWO mma16s. 2 CTAs/SM -> 256 thr/SM
//  -> 256 regs/thread for the doubled accumulators.
// ---------------------------------------------------------------------------
#define KTILE_B 16384                          // 64*128*2
#define VTILE_B 16384                          // 128*64*2
#define QROW_B  288                            // 256B data + 32B pad
#define QS_BYTES (128 * QROW_B)                // 36864
#define FL_SMEM_BYTES (QS_BYTES + 2 * (KTILE_B + VTILE_B))   // 102400
#define FL_THREADS 128

__device__ __forceinline__ void stage_tile(const __nv_bfloat16* __restrict__ Kg,
                                           const __nv_bfloat16* __restrict__ Vt,
                                           uint32_t dK, uint32_t dV, int tid) {
    #pragma unroll
    for (int u = 0; u < 8; u++) {              // K: 64 rows x 16 chunks(16B)
        const int h = u * FL_THREADS + tid;
        const int row = h >> 4, c = h & 15;
        const int c2 = ((((c >> 1) + row) & 7) << 1) | (c & 1);
        asm volatile("cp.async.cg.shared.global [%0], [%1], 16;"
                     :: "r"(dK + row * 256 + c2 * 16), "l"(Kg + row * CH + c * 8));
    }
    #pragma unroll
    for (int u = 0; u < 8; u++) {              // V: 128 rows x 8 chunks(16B)
        const int h = u * FL_THREADS + tid;
        const int row = h >> 3, c = h & 7;
        const int c2 = ((((c >> 1) + row) & 3) << 1) | (c & 1);
        asm volatile("cp.async.cg.shared.global [%0], [%1], 16;"
                     :: "r"(dV + row * 128 + c2 * 16), "l"(Vt + (size_t)row * NTOK + c * 8));
    }
    asm volatile("cp.async.commit_group;");
}

__global__ void __launch_bounds__(FL_THREADS, 2) flash_mma() {
    extern __shared__ char smc[];
    const uint32_t smem_base = (uint32_t)__cvta_generic_to_shared(smc);
    const uint32_t kv_base = smem_base + QS_BYTES;

    const int blk = blockIdx.x;
    const int b = blk >> 5;
    const int qbase = (blk & 31) * 128;
    const int tid = threadIdx.x;
    const int w = tid >> 5, l = tid & 31, g = l >> 2, t = l & 3;
    const int r1 = w * 32 + g;                 // set0: r1, r1+8; set1: r1+16, r1+24

    // stage Q into smem: bf16-packed, QSC folded (one full row per thread)
    const float* Qg = g_q + (size_t)(b * NTOK + qbase) * CH;
    {
        const int row = tid;                   // 0..127
        const float* src = &Qg[(size_t)row * CH];
        uint4* dst = (uint4*)(smc + row * QROW_B);
        #pragma unroll
        for (int i = 0; i < 16; i++) {
            float4 a  = *(const float4*)&src[i * 8];
            float4 b2 = *(const float4*)&src[i * 8 + 4];
            uint4 o;
            o.x = bfpack(a.x * QSC,  a.y * QSC);
            o.y = bfpack(a.z * QSC,  a.w * QSC);
            o.z = bfpack(b2.x * QSC, b2.y * QSC);
            o.w = bfpack(b2.z * QSC, b2.w * QSC);
            dst[i] = o;
        }
    }

    float oacc[2][16][4];
    #pragma unroll
    for (int s = 0; s < 2; s++)
        #pragma unroll
        for (int nt = 0; nt < 16; nt++)
            #pragma unroll
            for (int c = 0; c < 4; c++) oacc[s][nt][c] = 0.f;
    float mst[4] = {-1e30f, -1e30f, -1e30f, -1e30f};
    float lst[4] = {0.f, 0.f, 0.f, 0.f};

    const __nv_bfloat16* KgB = g_kb + (size_t)b * NTOK * CH;   // [key][ch]
    const __nv_bfloat16* VgB = g_vb + (size_t)b * CH * NTOK;   // [ch][key]

    stage_tile(KgB, VgB, kv_base, kv_base + KTILE_B, tid);

    const char* qr0 = smc + r1 * QROW_B + t * 8;
    const char* qr1 = smc + (r1 + 8) * QROW_B + t * 8;
    const char* qr2 = smc + (r1 + 16) * QROW_B + t * 8;
    const char* qr3 = smc + (r1 + 24) * QROW_B + t * 8;

    #pragma unroll 1
    for (int jt = 0; jt < 64; jt++) {
        if (jt < 63) {
            const uint32_t nb = kv_base + ((jt + 1) & 1) * (KTILE_B + VTILE_B);
            stage_tile(KgB + (size_t)(jt + 1) * 64 * CH,
                       VgB + (size_t)(jt + 1) * 64,
                       nb, nb + KTILE_B, tid);
            asm volatile("cp.async.wait_group 1;");
        } else {
            asm volatile("cp.async.wait_group 0;");
        }
        __syncthreads();   // staging of jt visible; Q ready on jt==0

        const __nv_bfloat16* Kb =
            (const __nv_bfloat16*)(smc + QS_BYTES + (jt & 1) * (KTILE_B + VTILE_B));
        const __nv_bfloat16* Vb = Kb + KTILE_B / 2;

        // ---- S = (Q*qsc) @ K^T : each K fragment feeds both A-sets ----
        float sacc[2][8][4];
        #pragma unroll
        for (int s = 0; s < 2; s++)
            #pragma unroll
            for (int nt = 0; nt < 8; nt++)
                #pragma unroll
                for (int c = 0; c < 4; c++) sacc[s][nt][c] = 0.f;

        #pragma unroll
        for (int m = 0; m < 8; m++) {
            const uint2 q0 = *(const uint2*)(qr0 + m * 32);
            const uint2 q1 = *(const uint2*)(qr1 + m * 32);
            const uint2 q2 = *(const uint2*)(qr2 + m * 32);
            const uint2 q3 = *(const uint2*)(qr3 + m * 32);
            const unsigned qa0[4] = {q0.x, q1.x, q0.y, q1.y};
            const unsigned qa1[4] = {q2.x, q3.x, q2.y, q3.y};
            const int moff = ((m + g) & 7) * 16 + 4 * t;
            #pragma unroll
            for (int nt = 0; nt < 8; nt++) {
                const uint2 kv = *(const uint2*)&Kb[(nt*8 + g) * 128 + moff];
                mma16(sacc[0][nt], qa0, kv.x, kv.y);
                mma16(sacc[1][nt], qa1, kv.x, kv.y);
            }
        }

        // ---- online softmax (exp2 domain, quad-local), both sets ----
        bool allone = true;
        float al[4];
        #pragma unroll
        for (int s = 0; s < 2; s++) {
            float mx1 = -1e30f, mx2 = -1e30f;
            #pragma unroll
            for (int nt = 0; nt < 8; nt++) {
                mx1 = fmaxf(mx1, fmaxf(sacc[s][nt][0], sacc[s][nt][1]));
                mx2 = fmaxf(mx2, fmaxf(sacc[s][nt][2], sacc[s][nt][3]));
            }
            #pragma unroll
            for (int off = 1; off < 4; off <<= 1) {
                mx1 = fmaxf(mx1, __shfl_xor_sync(0xffffffffu, mx1, off));
                mx2 = fmaxf(mx2, __shfl_xor_sync(0xffffffffu, mx2, off));
            }
            const float mn1 = fmaxf(mst[2*s], mx1), mn2 = fmaxf(mst[2*s+1], mx2);
            al[2*s]   = ex2(mst[2*s]   - mn1);
            al[2*s+1] = ex2(mst[2*s+1] - mn2);
            float rs1 = 0.f, rs2 = 0.f;
            #pragma unroll
            for (int nt = 0; nt < 8; nt++) {
                sacc[s][nt][0] = ex2(sacc[s][nt][0] - mn1);
                sacc[s][nt][1] = ex2(sacc[s][nt][1] - mn1);
                sacc[s][nt][2] = ex2(sacc[s][nt][2] - mn2);
                sacc[s][nt][3] = ex2(sacc[s][nt][3] - mn2);
                rs1 += sacc[s][nt][0] + sacc[s][nt][1];
                rs2 += sacc[s][nt][2] + sacc[s][nt][3];
            }
            #pragma unroll
            for (int off = 1; off < 4; off <<= 1) {
                rs1 += __shfl_xor_sync(0xffffffffu, rs1, off);
                rs2 += __shfl_xor_sync(0xffffffffu, rs2, off);
            }
            lst[2*s]   = lst[2*s]   * al[2*s]   + rs1;
            lst[2*s+1] = lst[2*s+1] * al[2*s+1] + rs2;
            mst[2*s] = mn1;  mst[2*s+1] = mn2;
            allone = allone && (al[2*s] == 1.0f) && (al[2*s+1] == 1.0f);
        }
        const bool noresc = __all_sync(0xffffffffu, allone);
        if (!noresc) {
            #pragma unroll
            for (int s = 0; s < 2; s++)
                #pragma unroll
                for (int nt = 0; nt < 16; nt++) {
                    oacc[s][nt][0] *= al[2*s];    oacc[s][nt][1] *= al[2*s];
                    oacc[s][nt][2] *= al[2*s+1];  oacc[s][nt][3] *= al[2*s+1];
                }
        }

        // ---- O += P @ V : each V fragment feeds both sets ----
        #pragma unroll
        for (int kt = 0; kt < 4; kt++) {
            unsigned ar0[4], ar1[4];
            ar0[0] = bfpack(sacc[0][2*kt    ][0], sacc[0][2*kt    ][1]);
            ar0[1] = bfpack(sacc[0][2*kt    ][2], sacc[0][2*kt    ][3]);
            ar0[2] = bfpack(sacc[0][2*kt + 1][0], sacc[0][2*kt + 1][1]);
            ar0[3] = bfpack(sacc[0][2*kt + 1][2], sacc[0][2*kt + 1][3]);
            ar1[0] = bfpack(sacc[1][2*kt    ][0], sacc[1][2*kt    ][1]);
            ar1[1] = bfpack(sacc[1][2*kt    ][2], sacc[1][2*kt    ][3]);
            ar1[2] = bfpack(sacc[1][2*kt + 1][0], sacc[1][2*kt + 1][1]);
            ar1[3] = bfpack(sacc[1][2*kt + 1][2], sacc[1][2*kt + 1][3]);
            const int koff = ((kt + g) & 3) * 16 + 4 * t;
            #pragma unroll
            for (int nt = 0; nt < 16; nt++) {
                const uint2 vv = *(const uint2*)&Vb[(nt*8 + g) * 64 + koff];
                mma16(oacc[0][nt], ar0, vv.x, vv.y);
                mma16(oacc[1][nt], ar1, vv.x, vv.y);
            }
        }
        __syncthreads();   // done reading buf[jt&1]
    }

    float* Og = g_attn + (size_t)(b * NTOK + qbase) * CH;
    #pragma unroll
    for (int s = 0; s < 2; s++) {
        const float inv1 = 1.0f / lst[2*s], inv2 = 1.0f / lst[2*s+1];
        const int ra = r1 + 16 * s;
        #pragma unroll
        for (int nt = 0; nt < 16; nt++) {
            const int ch = nt * 8 + 2 * t;
            float2 v0 = {oacc[s][nt][0] * inv1, oacc[s][nt][1] * inv1};
            float2 v1 = {oacc[s][nt][2] * inv2, oacc[s][nt][3] * inv2};
            *(float2*)&Og[(size_t)ra * CH + ch]       = v0;
            *(float2*)&Og[(size_t)(ra + 8) * CH + ch] = v1;
        }
    }
}

// ---------------------------------------------------------------------------
// K5: output projection via tf32 mma + bias + residual (unchanged)
// ---------------------------------------------------------------------------
__global__ void __launch_bounds__(256) proj_mma(const float* __restrict__ W,
                                                const float* __restrict__ bias,
                                                float* __restrict__ out) {
    extern __shared__ unsigned Ws[];
    const int tid = threadIdx.x;
    const int w = tid >> 5, l = tid & 31, g = l >> 2, t = l & 3;

    #pragma unroll
    for (int o = 0; o < 2; o++) {
        const int n = o * 64 + w * 8 + g;
        #pragma unroll
        for (int i = 0; i < 16; i++) {
            unsigned v0 = f2tf(W[n * CH + i*8 + t]);
            unsigned v1 = f2tf(W[n * CH + i*8 + t + 4]);
            const int qs = (4*i + t) ^ ((n & 3) << 2);
            *(uint2*)&Ws[n * CH + 2 * qs] = make_uint2(v0, v1);
        }
    }
    __syncthreads();

    const int m0 = blockIdx.x * 128;
    const int gm = m0 + w * 16 + g;
    unsigned aa[16][4];
    #pragma unroll
    for (int kt = 0; kt < 16; kt++) {
        aa[kt][0] = f2tf(g_attn[(size_t)gm       * CH + kt*8 + t    ]);
        aa[kt][1] = f2tf(g_attn[(size_t)(gm + 8) * CH + kt*8 + t    ]);
        aa[kt][2] = f2tf(g_attn[(size_t)gm       * CH + kt*8 + t + 4]);
        aa[kt][3] = f2tf(g_attn[(size_t)(gm + 8) * CH + kt*8 + t + 4]);
    }

    float acc[16][4];
    #pragma unroll
    for (int nt = 0; nt < 16; nt++)
        #pragma unroll
        for (int c = 0; c < 4; c++) acc[nt][c] = 0.f;

    const int sw = (g & 3) << 2;
    #pragma unroll
    for (int kt = 0; kt < 16; kt++) {
        const int qs = (kt * 4 + t) ^ sw;
        #pragma unroll
        for (int nt = 0; nt < 16; nt++) {
            uint2 b = *(uint2*)&Ws[(nt*8 + g) * CH + 2 * qs];
            mma8(acc[nt], aa[kt], b.x, b.y);
        }
    }

    const int bb = m0 >> 12;
    const int tok = (m0 & (NTOK - 1)) + w * 16 + g;
    #pragma unroll
    for (int nt = 0; nt < 16; nt++) {
        #pragma unroll
        for (int c = 0; c < 2; c++) {
            const int ch = nt * 8 + 2 * t + c;
            const float bo = bias[ch];
            const size_t a0 = ((size_t)bb * CH + ch) * NTOK + tok;
            out[a0]     = acc[nt][c]     + bo + g_normed[a0];
            out[a0 + 8] = acc[nt][c + 2] + bo + g_normed[a0 + 8];
        }
    }
}

// ---------------------------------------------------------------------------
extern "C" void kernel_launch(void* const* d_in, const int* in_sizes, int n_in,
                              void* d_out, int out_size) {
    const float* x   = (const float*)d_in[0];
    const float* gnw = (const float*)d_in[1];
    const float* gnb = (const float*)d_in[2];
    const float* Wq  = (const float*)d_in[3];
    const float* bq  = (const float*)d_in[4];
    const float* Wk  = (const float*)d_in[5];
    const float* bk  = (const float*)d_in[6];
    const float* Wv  = (const float*)d_in[7];
    const float* bv  = (const float*)d_in[8];
    const float* Wp  = (const float*)d_in[9];
    const float* bp  = (const float*)d_in[10];
    float* out = (float*)d_out;

    cudaFuncSetAttribute(flash_mma, cudaFuncAttributeMaxDynamicSharedMemorySize, FL_SMEM_BYTES);
    cudaFuncSetAttribute(qkv_mma,  cudaFuncAttributeMaxDynamicSharedMemorySize, 65536);
    cudaFuncSetAttribute(proj_mma, cudaFuncAttributeMaxDynamicSharedMemorySize, 65536);

    gn_stats<<<BATCH * NGRP, 256>>>(x);
    gn_apply<<<(BATCH * CH * NTOK / 4) / 256, 256>>>(x, gnw, gnb);
    qkv_mma<<<dim3(BATCH * NTOK / 128, 3), 256, 65536>>>(Wq, bq, Wk, bk, Wv, bv);
    flash_mma<<<BATCH * (NTOK / 128), FL_THREADS, FL_SMEM_BYTES>>>();
    proj_mma<<<BATCH * NTOK / 128, 256, 65536>>>(Wp, bp, out);
}